// round 1
// baseline (speedup 1.0000x reference)
#include <cuda_runtime.h>

#define N_THREADS  256
#define NODES_PB   128     // nodes per block
#define GRAPHS_PB  8       // graphs per block (16 nodes each)
#define HID        128
#define OBS        64
#define XS         132     // padded row stride for s_x (min bank phases, float4-aligned)
#define OS         68      // padded row stride for s_obs

// smem layout (floats):
//   s_x    : NODES_PB * XS      = 16896
//   s_w    : HID * HID          = 16384 (w_emb uses first 64 rows)
//   s_obs  : NODES_PB * OS      =  8704
//   s_xbar : GRAPHS_PB * HID    =  1024
//   s_m    : GRAPHS_PB * HID    =  1024
// total = 44032 floats = 176128 bytes
#define SMEM_FLOATS (NODES_PB*XS + HID*HID + NODES_PB*OS + 2*GRAPHS_PB*HID)

__device__ __forceinline__ float fast_tanh(float v) {
    // tanh(v) = 1 - 2/(e^{2v}+1); __expf accurate to ~2 ulp, saturates correctly at +-inf
    float e = __expf(2.0f * v);
    return 1.0f - __fdividef(2.0f, e + 1.0f);
}

__global__ __launch_bounds__(N_THREADS, 1)
void gcn_critic_kernel(const float* __restrict__ cent_obs,
                       const float* __restrict__ w_emb,
                       const float* __restrict__ b_emb,
                       const float* __restrict__ w_gcn,
                       const float* __restrict__ b_gcn,
                       const float* __restrict__ w_fc1,
                       const float* __restrict__ b_fc1,
                       float* __restrict__ out)
{
    extern __shared__ float sm[];
    float* s_x    = sm;                        // [128][132]
    float* s_w    = s_x + NODES_PB * XS;       // [128][128]
    float* s_obs  = s_w + HID * HID;           // [128][68]
    float* s_xbar = s_obs + NODES_PB * OS;     // [8][128]
    float* s_m    = s_xbar + GRAPHS_PB * HID;  // [8][128]

    const int t    = threadIdx.x;
    const int b    = blockIdx.x;
    const int n    = t >> 1;        // local node 0..127 (2 threads per node)
    const int half = t & 1;
    const int hb   = half * 64;     // this thread owns hid columns [hb, hb+64)
    const long node0 = (long)b * NODES_PB;

    // ---- stage w_emb (64x128) and obs tile (128x64, padded) ----
    {
        const float4* src = (const float4*)w_emb;
        float4* dst = (float4*)s_w;
        #pragma unroll
        for (int i = 0; i < (OBS*HID/4)/N_THREADS; i++)       // 8
            dst[t + i*N_THREADS] = src[t + i*N_THREADS];

        const float4* osrc = (const float4*)(cent_obs + node0 * OBS);
        #pragma unroll
        for (int i = 0; i < (NODES_PB*OBS/4)/N_THREADS; i++) { // 8
            int idx = t + i*N_THREADS;
            int row = idx >> 4;          // 16 float4 per obs row
            int c4  = idx & 15;
            float4 v = osrc[idx];
            *(float4*)(s_obs + row*OS + c4*4) = v;
        }
    }
    __syncthreads();

    // ---- Phase 1: embedding  x[n][hb..hb+63] = obs[n] @ w_emb + b_emb ----
    for (int h0 = 0; h0 < 64; h0 += 8) {
        const int h = hb + h0;
        float4 bv0 = *(const float4*)(b_emb + h);
        float4 bv1 = *(const float4*)(b_emb + h + 4);
        float acc0=bv0.x, acc1=bv0.y, acc2=bv0.z, acc3=bv0.w;
        float acc4=bv1.x, acc5=bv1.y, acc6=bv1.z, acc7=bv1.w;
        #pragma unroll 4
        for (int k4 = 0; k4 < OBS; k4 += 4) {
            float4 av = *(const float4*)(s_obs + n*OS + k4);
            float aa[4] = {av.x, av.y, av.z, av.w};
            #pragma unroll
            for (int kk = 0; kk < 4; kk++) {
                const float a = aa[kk];
                const float* wr = s_w + (k4 + kk)*HID + h;
                float4 w0 = *(const float4*)wr;
                float4 w1 = *(const float4*)(wr + 4);
                acc0 += a*w0.x; acc1 += a*w0.y; acc2 += a*w0.z; acc3 += a*w0.w;
                acc4 += a*w1.x; acc5 += a*w1.y; acc6 += a*w1.z; acc7 += a*w1.w;
            }
        }
        *(float4*)(s_x + n*XS + h)     = make_float4(acc0, acc1, acc2, acc3);
        *(float4*)(s_x + n*XS + h + 4) = make_float4(acc4, acc5, acc6, acc7);
    }
    __syncthreads();

    // ---- GCN layers: agg == per-graph mean (deg==16 everywhere, norm==1/16) ----
    for (int l = 0; l < 2; l++) {
        // stage w_gcn[l] (s_w readers from prior stage are past the last syncthreads)
        {
            const float4* src = (const float4*)(w_gcn + l*HID*HID);
            float4* dst = (float4*)s_w;
            #pragma unroll
            for (int i = 0; i < (HID*HID/4)/N_THREADS; i++)   // 16
                dst[t + i*N_THREADS] = src[t + i*N_THREADS];
        }
        // xbar[g] = mean of 16 node rows  (each thread: 4 columns of one graph)
        {
            const int g  = t >> 5;
            const int h0 = (t & 31) << 2;
            float sx=0.f, sy=0.f, sz=0.f, sww=0.f;
            #pragma unroll
            for (int i = 0; i < 16; i++) {
                float4 v = *(const float4*)(s_x + (g*16 + i)*XS + h0);
                sx += v.x; sy += v.y; sz += v.z; sww += v.w;
            }
            const float inv = 0.0625f;
            *(float4*)(s_xbar + g*HID + h0) = make_float4(sx*inv, sy*inv, sz*inv, sww*inv);
        }
        __syncthreads();
        // m[g] = xbar[g] @ W + b_gcn[l]
        {
            const int g  = t >> 5;                // warp-constant -> broadcast LDS
            const int h0 = (t & 31) << 2;
            float4 acc = *(const float4*)(b_gcn + l*HID + h0);
            #pragma unroll 8
            for (int k = 0; k < HID; k++) {
                const float a = s_xbar[g*HID + k];
                float4 wv = *(const float4*)(s_w + k*HID + h0);
                acc.x += a*wv.x; acc.y += a*wv.y; acc.z += a*wv.z; acc.w += a*wv.w;
            }
            *(float4*)(s_m + g*HID + h0) = acc;
        }
        __syncthreads();
        // x = tanh(m[graph] + x)   (residual)
        {
            const int g = n >> 4;
            #pragma unroll
            for (int h0 = 0; h0 < 64; h0 += 4) {
                const int h = hb + h0;
                float4 xv = *(const float4*)(s_x + n*XS + h);
                float4 mv = *(const float4*)(s_m + g*HID + h);
                xv.x = fast_tanh(xv.x + mv.x);
                xv.y = fast_tanh(xv.y + mv.y);
                xv.z = fast_tanh(xv.z + mv.z);
                xv.w = fast_tanh(xv.w + mv.w);
                *(float4*)(s_x + n*XS + h) = xv;
            }
        }
        __syncthreads();
    }

    // ---- head: out[g] = mean_n( x[n] . w_fc1 ) + b_fc1 ; warp w <-> graph w ----
    {
        float p = 0.f;
        #pragma unroll
        for (int h0 = 0; h0 < 64; h0 += 4) {
            float4 xv = *(const float4*)(s_x + n*XS + hb + h0);
            float4 wv = *(const float4*)(w_fc1 + hb + h0);
            p += xv.x*wv.x + xv.y*wv.y + xv.z*wv.z + xv.w*wv.w;
        }
        #pragma unroll
        for (int off = 16; off; off >>= 1)
            p += __shfl_xor_sync(0xffffffffu, p, off);
        if ((t & 31) == 0)
            out[b*GRAPHS_PB + (t >> 5)] = p * 0.0625f + b_fc1[0];
    }
}

extern "C" void kernel_launch(void* const* d_in, const int* in_sizes, int n_in,
                              void* d_out, int out_size) {
    const float* cent_obs = (const float*)d_in[0];
    const float* w_emb    = (const float*)d_in[1];
    const float* b_emb    = (const float*)d_in[2];
    const float* w_gcn    = (const float*)d_in[3];
    const float* b_gcn    = (const float*)d_in[4];
    const float* w_fc1    = (const float*)d_in[5];
    const float* b_fc1    = (const float*)d_in[6];
    // d_in[7]/d_in[8] (edge_src/edge_dst) are the fixed complete graph; the
    // symmetric-norm aggregation reduces exactly to a per-graph mean, so they
    // are not needed.
    float* out = (float*)d_out;

    const int batch  = out_size;               // 8192 graphs
    const int blocks = batch / GRAPHS_PB;      // 1024
    const size_t smem_bytes = SMEM_FLOATS * sizeof(float);  // 176128

    cudaFuncSetAttribute(gcn_critic_kernel,
                         cudaFuncAttributeMaxDynamicSharedMemorySize,
                         (int)smem_bytes);

    gcn_critic_kernel<<<blocks, N_THREADS, smem_bytes>>>(
        cent_obs, w_emb, b_emb, w_gcn, b_gcn, w_fc1, b_fc1, out);
}

// round 2
// speedup vs baseline: 2.4994x; 2.4994x over previous
#include <cuda_runtime.h>

#define N_THREADS 256
#define HID       128
#define OBS       64
#define OTS       132   // padded stride for s_obsT rows

// smem floats: s_w 16384 + s_obsT 64*132=8448 + s_xbar 1024 + s_m 1024 = 26880 (105 KB)
#define SMEM_FLOATS (HID*HID + OBS*OTS + 2*8*HID)

__device__ __forceinline__ float htanh(float x) {
    float y;
    asm("tanh.approx.f32 %0, %1;" : "=f"(y) : "f"(x));
    return y;
}

__global__ __launch_bounds__(N_THREADS, 2)
void gcn_critic_kernel(const float* __restrict__ cent_obs,
                       const float* __restrict__ w_emb,
                       const float* __restrict__ b_emb,
                       const float* __restrict__ w_gcn,
                       const float* __restrict__ b_gcn,
                       const float* __restrict__ w_fc1,
                       const float* __restrict__ b_fc1,
                       float* __restrict__ out)
{
    extern __shared__ float sm[];
    float* s_w    = sm;                    // [128][128] (w_emb uses rows 0..63)
    float* s_obsT = s_w + HID * HID;       // [64][132]  obs transposed
    float* s_xbar = s_obsT + OBS * OTS;    // [8][128]
    float* s_m    = s_xbar + 8 * HID;      // [8][128]

    const int t  = threadIdx.x;
    const int b  = blockIdx.x;
    const int tx = t & 15;                 // hid tile: cols tx*8 .. tx*8+7
    const int ty = t >> 4;                 // node tile: nodes ty*8 .. ty*8+7
    const int g  = t >> 5;                 // graph = warp id (nodes ty*8.. all in graph ty/2)
    const long node0 = (long)b * 128;

    // ---- stage w_emb (64x128) + obs transposed ----
    {
        const float4* src = (const float4*)w_emb;
        float4* dst = (float4*)s_w;
        #pragma unroll
        for (int i = 0; i < 8; i++)
            dst[t + i * N_THREADS] = src[t + i * N_THREADS];

        const float4* osrc = (const float4*)(cent_obs + node0 * OBS);
        #pragma unroll
        for (int i = 0; i < 8; i++) {
            int idx  = t + i * N_THREADS;
            int node = idx >> 4;      // 16 float4 per obs row
            int k4   = (idx & 15) * 4;
            float4 v = osrc[idx];
            s_obsT[(k4 + 0) * OTS + node] = v.x;
            s_obsT[(k4 + 1) * OTS + node] = v.y;
            s_obsT[(k4 + 2) * OTS + node] = v.z;
            s_obsT[(k4 + 3) * OTS + node] = v.w;
        }
    }
    __syncthreads();

    // ---- embedding: acc[n][c] = obs[node ty*8+n] @ w_emb[:, tx*8+c] + b ----
    float acc[8][8];
    {
        float4 b0 = *(const float4*)(b_emb + tx * 8);
        float4 b1 = *(const float4*)(b_emb + tx * 8 + 4);
        #pragma unroll
        for (int n = 0; n < 8; n++) {
            acc[n][0] = b0.x; acc[n][1] = b0.y; acc[n][2] = b0.z; acc[n][3] = b0.w;
            acc[n][4] = b1.x; acc[n][5] = b1.y; acc[n][6] = b1.z; acc[n][7] = b1.w;
        }
    }
    #pragma unroll 8
    for (int k = 0; k < OBS; k++) {
        float4 a0 = *(const float4*)(s_obsT + k * OTS + ty * 8);
        float4 a1 = *(const float4*)(s_obsT + k * OTS + ty * 8 + 4);
        float4 w0 = *(const float4*)(s_w + k * HID + tx * 8);
        float4 w1 = *(const float4*)(s_w + k * HID + tx * 8 + 4);
        float av[8] = {a0.x, a0.y, a0.z, a0.w, a1.x, a1.y, a1.z, a1.w};
        float wv[8] = {w0.x, w0.y, w0.z, w0.w, w1.x, w1.y, w1.z, w1.w};
        #pragma unroll
        for (int n = 0; n < 8; n++)
            #pragma unroll
            for (int c = 0; c < 8; c++)
                acc[n][c] += av[n] * wv[c];
    }
    __syncthreads();   // done with s_w (emb) and s_obsT

    // ---- GCN layers (agg == per-graph mean: deg==16 everywhere, norm==1/16) ----
    #pragma unroll
    for (int l = 0; l < 2; l++) {
        // stage w_gcn[l]
        {
            const float4* src = (const float4*)(w_gcn + l * HID * HID);
            float4* dst = (float4*)s_w;
            #pragma unroll
            for (int i = 0; i < 16; i++)
                dst[t + i * N_THREADS] = src[t + i * N_THREADS];
        }
        // xbar[g][tx*8..] : sum over the warp's 16 nodes (8 in regs + partner ty)
        {
            float p[8];
            #pragma unroll
            for (int c = 0; c < 8; c++) {
                p[c] = acc[0][c];
                #pragma unroll
                for (int n = 1; n < 8; n++) p[c] += acc[n][c];
            }
            #pragma unroll
            for (int c = 0; c < 8; c++)
                p[c] += __shfl_xor_sync(0xffffffffu, p[c], 16);
            if (!(ty & 1)) {
                const float inv = 0.0625f;
                *(float4*)(s_xbar + g * HID + tx * 8) =
                    make_float4(p[0]*inv, p[1]*inv, p[2]*inv, p[3]*inv);
                *(float4*)(s_xbar + g * HID + tx * 8 + 4) =
                    make_float4(p[4]*inv, p[5]*inv, p[6]*inv, p[7]*inv);
            }
        }
        __syncthreads();

        // matvec: warps 0..3, warp w serves graphs 2w,2w+1 (one W-row read, 2 graphs)
        if (g < 4) {
            const int lane = t & 31;
            const int c4 = lane * 4;
            float4 bias = *(const float4*)(b_gcn + l * HID + c4);
            float4 m0 = bias, m1 = bias;
            const float* xb0 = s_xbar + (2 * g) * HID;
            const float* xb1 = xb0 + HID;
            #pragma unroll 8
            for (int k = 0; k < HID; k++) {
                float4 wv = *(const float4*)(s_w + k * HID + c4);
                float a0 = xb0[k], a1 = xb1[k];
                m0.x += a0 * wv.x; m0.y += a0 * wv.y; m0.z += a0 * wv.z; m0.w += a0 * wv.w;
                m1.x += a1 * wv.x; m1.y += a1 * wv.y; m1.z += a1 * wv.z; m1.w += a1 * wv.w;
            }
            *(float4*)(s_m + (2 * g) * HID + c4)     = m0;
            *(float4*)(s_m + (2 * g + 1) * HID + c4) = m1;
        }
        __syncthreads();

        // x = tanh(x + m[graph])  (in registers)
        {
            float4 m0 = *(const float4*)(s_m + g * HID + tx * 8);
            float4 m1 = *(const float4*)(s_m + g * HID + tx * 8 + 4);
            float mv[8] = {m0.x, m0.y, m0.z, m0.w, m1.x, m1.y, m1.z, m1.w};
            #pragma unroll
            for (int n = 0; n < 8; n++)
                #pragma unroll
                for (int c = 0; c < 8; c++)
                    acc[n][c] = htanh(acc[n][c] + mv[c]);
        }
        // no trailing sync needed: next-iter writers are fenced by syncs above
    }

    // ---- head: out[g] = mean_n(x . w_fc1) + b ; warp == graph ----
    {
        float4 wf0 = *(const float4*)(w_fc1 + tx * 8);
        float4 wf1 = *(const float4*)(w_fc1 + tx * 8 + 4);
        float wv[8] = {wf0.x, wf0.y, wf0.z, wf0.w, wf1.x, wf1.y, wf1.z, wf1.w};
        float p = 0.f;
        #pragma unroll
        for (int n = 0; n < 8; n++)
            #pragma unroll
            for (int c = 0; c < 8; c++)
                p += acc[n][c] * wv[c];
        #pragma unroll
        for (int off = 16; off; off >>= 1)
            p += __shfl_xor_sync(0xffffffffu, p, off);
        if ((t & 31) == 0)
            out[b * 8 + g] = p * 0.0625f + b_fc1[0];
    }
}

extern "C" void kernel_launch(void* const* d_in, const int* in_sizes, int n_in,
                              void* d_out, int out_size) {
    const float* cent_obs = (const float*)d_in[0];
    const float* w_emb    = (const float*)d_in[1];
    const float* b_emb    = (const float*)d_in[2];
    const float* w_gcn    = (const float*)d_in[3];
    const float* b_gcn    = (const float*)d_in[4];
    const float* w_fc1    = (const float*)d_in[5];
    const float* b_fc1    = (const float*)d_in[6];
    // edge_src/edge_dst (d_in[7], d_in[8]): fixed complete graph -> per-graph mean
    float* out = (float*)d_out;

    const int blocks = out_size / 8;                       // 1024
    const size_t smem_bytes = SMEM_FLOATS * sizeof(float); // 107520

    cudaFuncSetAttribute(gcn_critic_kernel,
                         cudaFuncAttributeMaxDynamicSharedMemorySize,
                         (int)smem_bytes);

    gcn_critic_kernel<<<blocks, N_THREADS, smem_bytes>>>(
        cent_obs, w_emb, b_emb, w_gcn, b_gcn, w_fc1, b_fc1, out);
}

// round 4
// speedup vs baseline: 2.6762x; 1.0707x over previous
#include <cuda_runtime.h>
#include <cuda_bf16.h>
#include <stdint.h>

#define NTHR 256
#define HID  128
#define OBS  64
#define XS   132   // f32 stride of s_x rows
#define OHS  68    // u32 stride of s_obsHL rows

// w_emb pre-packed as m16n8k16 B-fragments: [hi 4096 u32][lo 4096 u32]
// index: ((kt*16 + j)*32 + lane)*2 + p   (kt=ktile 0..3, j=ntile 0..15, p=b0/b1)
__device__ __align__(16) uint32_t g_Bfrag[8192];

__device__ __forceinline__ uint32_t bf16_hi_bits(float v) {
    return (uint32_t)__bfloat16_as_ushort(__float2bfloat16(v));
}

__global__ void prep_kernel(const float* __restrict__ w_emb) {
    int idx  = blockIdx.x * 128 + threadIdx.x;   // 0..2047
    int lane = idx & 31;
    int j    = (idx >> 5) & 15;
    int kt   = idx >> 9;
    int g    = lane >> 2, tid = lane & 3;
    int n    = j * 8 + g;
    int base = ((kt * 16 + j) * 32 + lane) * 2;
    #pragma unroll
    for (int p = 0; p < 2; p++) {
        int k0 = kt * 16 + tid * 2 + p * 8;
        float v0 = w_emb[k0 * HID + n];
        float v1 = w_emb[(k0 + 1) * HID + n];
        uint32_t h0 = bf16_hi_bits(v0), h1 = bf16_hi_bits(v1);
        uint32_t l0 = bf16_hi_bits(v0 - __uint_as_float(h0 << 16));
        uint32_t l1 = bf16_hi_bits(v1 - __uint_as_float(h1 << 16));
        g_Bfrag[base + p]        = (h1 << 16) | h0;
        g_Bfrag[4096 + base + p] = (l1 << 16) | l0;
    }
}

__device__ __forceinline__ float htanh(float x) {
    float y; asm("tanh.approx.f32 %0, %1;" : "=f"(y) : "f"(x)); return y;
}

__device__ __forceinline__ void mma_bf16(float& c0, float& c1, float& c2, float& c3,
                                         uint32_t a0, uint32_t a1, uint32_t a2, uint32_t a3,
                                         uint32_t b0, uint32_t b1) {
    asm volatile(
        "mma.sync.aligned.m16n8k16.row.col.f32.bf16.bf16.f32 "
        "{%0,%1,%2,%3}, {%4,%5,%6,%7}, {%8,%9}, {%0,%1,%2,%3};"
        : "+f"(c0), "+f"(c1), "+f"(c2), "+f"(c3)
        : "r"(a0), "r"(a1), "r"(a2), "r"(a3), "r"(b0), "r"(b1));
}

// ---- smem byte offsets ----
#define SM_X    0                     // 128*132*4 = 67584
#define SM_OBS  67584                 // 128*68*4  = 34816
#define SM_B    102400                // 8192 u32  = 32768  (hi then lo)
#define SM_W    67584                 // reuse OBS+B region after GEMM (65536)
#define SM_XBAR 135168                // 8*128 f32 = 4096
#define SM_M    139264                // 8*128 f32 = 4096
#define SM_RED  143360                // 32 f32
#define SM_TOT  143488

__global__ __launch_bounds__(NTHR, 1)
void gcn_critic_kernel(const float* __restrict__ cent_obs,
                       const float* __restrict__ b_emb,
                       const float* __restrict__ w_gcn,
                       const float* __restrict__ b_gcn,
                       const float* __restrict__ w_fc1,
                       const float* __restrict__ b_fc1,
                       float* __restrict__ out)
{
    extern __shared__ char smem[];
    float*    s_x    = (float*)(smem + SM_X);
    uint32_t* obsHL  = (uint32_t*)(smem + SM_OBS);
    uint32_t* sBhi   = (uint32_t*)(smem + SM_B);
    uint32_t* sBlo   = sBhi + 4096;
    float*    s_w    = (float*)(smem + SM_W);
    float*    s_xbar = (float*)(smem + SM_XBAR);
    float*    s_m    = (float*)(smem + SM_M);
    float*    s_red  = (float*)(smem + SM_RED);

    const int t    = threadIdx.x;
    const int wid  = t >> 5;
    const int lane = t & 31;
    const long node0 = (long)blockIdx.x * 128;

    // ---- stage B fragments (pre-packed) ----
    {
        const uint4* src = (const uint4*)g_Bfrag;
        uint4* dst = (uint4*)sBhi;
        #pragma unroll
        for (int i = 0; i < 8; i++)
            dst[t + i * NTHR] = src[t + i * NTHR];
    }
    // ---- stage obs as (hi<<16 | lo) bf16 pairs ----
    {
        const float4* osrc = (const float4*)(cent_obs + node0 * OBS);
        #pragma unroll
        for (int i = 0; i < 8; i++) {
            int idx  = t + i * NTHR;
            int node = idx >> 4;
            int k4   = (idx & 15) * 4;
            float4 v = osrc[idx];
            uint32_t u[4];
            float vv[4] = {v.x, v.y, v.z, v.w};
            #pragma unroll
            for (int e = 0; e < 4; e++) {
                uint32_t hb = bf16_hi_bits(vv[e]);
                uint32_t lb = bf16_hi_bits(vv[e] - __uint_as_float(hb << 16));
                u[e] = (hb << 16) | lb;
            }
            *(uint4*)(obsHL + node * OHS + k4) = make_uint4(u[0], u[1], u[2], u[3]);
        }
    }
    __syncthreads();

    // ---- embedding GEMM via HMMA: x[128 nodes][128 hid] = obs @ w_emb ----
    {
        const int g = lane >> 2, tid = lane & 3;
        const int r0 = wid * 16 + g;
        // A fragments (hi & lo), fragment order a0..a3 per ktile
        uint32_t aH[16], aL[16];
        #pragma unroll
        for (int kt = 0; kt < 4; kt++) {
            #pragma unroll
            for (int q = 0; q < 2; q++) {          // q=0: a0/a1 ; q=1: a2/a3
                const int k = kt * 16 + tid * 2 + q * 8;
                uint32_t u0 = obsHL[r0 * OHS + k];
                uint32_t u1 = obsHL[r0 * OHS + k + 1];
                aH[kt*4 + q*2 + 0] = (u1 & 0xffff0000u) | (u0 >> 16);
                aL[kt*4 + q*2 + 0] = (u1 << 16) | (u0 & 0xffffu);
                uint32_t w0 = obsHL[(r0 + 8) * OHS + k];
                uint32_t w1 = obsHL[(r0 + 8) * OHS + k + 1];
                aH[kt*4 + q*2 + 1] = (w1 & 0xffff0000u) | (w0 >> 16);
                aL[kt*4 + q*2 + 1] = (w1 << 16) | (w0 & 0xffffu);
            }
        }
        // fragment order is a0,a1,a2,a3 = [q0 row0, q0 row1, q1 row0, q1 row1]
        #pragma unroll
        for (int j = 0; j < 16; j++) {
            float c0 = 0.f, c1 = 0.f, c2 = 0.f, c3 = 0.f;
            #pragma unroll
            for (int kt = 0; kt < 4; kt++) {
                const int bi = ((kt * 16 + j) * 32 + lane) * 2;
                uint32_t bh0 = sBhi[bi], bh1 = sBhi[bi + 1];
                uint32_t bl0 = sBlo[bi], bl1 = sBlo[bi + 1];
                uint32_t a0 = aH[kt*4+0], a1 = aH[kt*4+1], a2 = aH[kt*4+2], a3 = aH[kt*4+3];
                uint32_t e0 = aL[kt*4+0], e1 = aL[kt*4+1], e2 = aL[kt*4+2], e3 = aL[kt*4+3];
                mma_bf16(c0, c1, c2, c3, a0, a1, a2, a3, bh0, bh1);   // hiA*hiB
                mma_bf16(c0, c1, c2, c3, e0, e1, e2, e3, bh0, bh1);   // loA*hiB
                mma_bf16(c0, c1, c2, c3, a0, a1, a2, a3, bl0, bl1);   // hiA*loB
            }
            float* xr = s_x + r0 * XS + j * 8 + tid * 2;
            xr[0] = c0; xr[1] = c1;
            xr[8 * XS] = c2; xr[8 * XS + 1] = c3;
        }
    }
    __syncthreads();   // s_x complete; obs/B region now dead -> becomes s_w

    // ---- load x into R2 register tiling + bias; stage w_gcn[0] ----
    const int tx = t & 15;   // hid cols tx*8..+7
    const int ty = t >> 4;   // nodes ty*8..+7
    const int g  = wid;      // graph = warp id

    float acc[8][8];
    {
        float4 be0 = *(const float4*)(b_emb + tx * 8);
        float4 be1 = *(const float4*)(b_emb + tx * 8 + 4);
        #pragma unroll
        for (int n = 0; n < 8; n++) {
            float4 x0 = *(const float4*)(s_x + (ty * 8 + n) * XS + tx * 8);
            float4 x1 = *(const float4*)(s_x + (ty * 8 + n) * XS + tx * 8 + 4);
            acc[n][0] = x0.x + be0.x; acc[n][1] = x0.y + be0.y;
            acc[n][2] = x0.z + be0.z; acc[n][3] = x0.w + be0.w;
            acc[n][4] = x1.x + be1.x; acc[n][5] = x1.y + be1.y;
            acc[n][6] = x1.z + be1.z; acc[n][7] = x1.w + be1.w;
        }
    }
    {
        const float4* src = (const float4*)w_gcn;
        float4* dst = (float4*)s_w;
        #pragma unroll
        for (int i = 0; i < 16; i++)
            dst[t + i * NTHR] = src[t + i * NTHR];
    }

    // ---- GCN layers (agg == per-graph mean: deg 16, norm 1/16) ----
    #pragma unroll
    for (int l = 0; l < 2; l++) {
        // xbar[g] from registers: 8 own nodes + partner half via shfl
        {
            float p[8];
            #pragma unroll
            for (int c = 0; c < 8; c++) {
                p[c] = acc[0][c];
                #pragma unroll
                for (int n = 1; n < 8; n++) p[c] += acc[n][c];
            }
            #pragma unroll
            for (int c = 0; c < 8; c++)
                p[c] += __shfl_xor_sync(0xffffffffu, p[c], 16);
            if (!(ty & 1)) {
                const float inv = 0.0625f;
                *(float4*)(s_xbar + g * HID + tx * 8) =
                    make_float4(p[0]*inv, p[1]*inv, p[2]*inv, p[3]*inv);
                *(float4*)(s_xbar + g * HID + tx * 8 + 4) =
                    make_float4(p[4]*inv, p[5]*inv, p[6]*inv, p[7]*inv);
            }
        }
        __syncthreads();

        // matvec: warps 0..3, warp w -> graphs 2w, 2w+1
        if (g < 4) {
            const int c4 = lane * 4;
            float4 bias = *(const float4*)(b_gcn + l * HID + c4);
            float4 m0 = bias, m1 = bias;
            const float* xb0 = s_xbar + (2 * g) * HID;
            const float* xb1 = xb0 + HID;
            #pragma unroll 8
            for (int k = 0; k < HID; k++) {
                float4 wv = *(const float4*)(s_w + k * HID + c4);
                float a0 = xb0[k], a1 = xb1[k];
                m0.x += a0 * wv.x; m0.y += a0 * wv.y; m0.z += a0 * wv.z; m0.w += a0 * wv.w;
                m1.x += a1 * wv.x; m1.y += a1 * wv.y; m1.z += a1 * wv.z; m1.w += a1 * wv.w;
            }
            *(float4*)(s_m + (2 * g) * HID + c4)     = m0;
            *(float4*)(s_m + (2 * g + 1) * HID + c4) = m1;
        }
        __syncthreads();

        // stage next layer's W (safe: matvec done)
        if (l == 0) {
            const float4* src = (const float4*)(w_gcn + HID * HID);
            float4* dst = (float4*)s_w;
            #pragma unroll
            for (int i = 0; i < 16; i++)
                dst[t + i * NTHR] = src[t + i * NTHR];
        }

        // x = tanh(x + m[graph])
        {
            float4 m0 = *(const float4*)(s_m + g * HID + tx * 8);
            float4 m1 = *(const float4*)(s_m + g * HID + tx * 8 + 4);
            float mv[8] = {m0.x, m0.y, m0.z, m0.w, m1.x, m1.y, m1.z, m1.w};
            #pragma unroll
            for (int n = 0; n < 8; n++)
                #pragma unroll
                for (int c = 0; c < 8; c++)
                    acc[n][c] = htanh(acc[n][c] + mv[c]);
        }
        __syncthreads();
    }

    // ---- head: out[g] = mean_n(x . w_fc1) + b ; warp == graph ----
    {
        float4 wf0 = *(const float4*)(w_fc1 + tx * 8);
        float4 wf1 = *(const float4*)(w_fc1 + tx * 8 + 4);
        float wv[8] = {wf0.x, wf0.y, wf0.z, wf0.w, wf1.x, wf1.y, wf1.z, wf1.w};
        float p = 0.f;
        #pragma unroll
        for (int n = 0; n < 8; n++)
            #pragma unroll
            for (int c = 0; c < 8; c++)
                p += acc[n][c] * wv[c];
        #pragma unroll
        for (int off = 16; off; off >>= 1)
            p += __shfl_xor_sync(0xffffffffu, p, off);
        if (lane == 0)
            out[blockIdx.x * 8 + g] = p * 0.0625f + b_fc1[0];
        (void)s_red;
    }
}

extern "C" void kernel_launch(void* const* d_in, const int* in_sizes, int n_in,
                              void* d_out, int out_size) {
    const float* cent_obs = (const float*)d_in[0];
    const float* w_emb    = (const float*)d_in[1];
    const float* b_emb    = (const float*)d_in[2];
    const float* w_gcn    = (const float*)d_in[3];
    const float* b_gcn    = (const float*)d_in[4];
    const float* w_fc1    = (const float*)d_in[5];
    const float* b_fc1    = (const float*)d_in[6];
    // edge_src/edge_dst: fixed complete graph -> per-graph mean; unused.
    float* out = (float*)d_out;

    prep_kernel<<<16, 128>>>(w_emb);

    cudaFuncSetAttribute(gcn_critic_kernel,
                         cudaFuncAttributeMaxDynamicSharedMemorySize, SM_TOT);

    const int blocks = out_size / 8;   // 1024
    gcn_critic_kernel<<<blocks, NTHR, SM_TOT>>>(
        cent_obs, b_emb, w_gcn, b_gcn, w_fc1, b_fc1, out);
}

// round 5
// speedup vs baseline: 4.3571x; 1.6281x over previous
#include <cuda_runtime.h>
#include <cuda_bf16.h>
#include <stdint.h>

#define HID  128
#define OBS  64
#define XBS  132      // float stride for s_xbar / s_m rows

// pre-packed MMA B-fragments (filled by prep_kernel):
// g_Bemb: w_emb, index ((kt*16+j)*32+lane)*2 + p ; hi at [0..4095], lo at +4096
__device__ __align__(16) uint32_t g_Bemb[8192];
// g_Wf: w_gcn, layer l: hi at l*16384, lo at l*16384+8192, same inner index (kt 0..7)
__device__ __align__(16) uint32_t g_Wf[32768];

__device__ __forceinline__ uint32_t bf16_hi_bits(float v) {
    return (uint32_t)__bfloat16_as_ushort(__float2bfloat16(v));
}
__device__ __forceinline__ uint32_t cvt_bf16x2(float hi_elt, float lo_elt) {
    uint32_t r;
    asm("cvt.rn.bf16x2.f32 %0, %1, %2;" : "=r"(r) : "f"(hi_elt), "f"(lo_elt));
    return r;   // [31:16]=bf16(hi_elt), [15:0]=bf16(lo_elt)
}
__device__ __forceinline__ float lo_f(uint32_t u) { return __uint_as_float(u << 16); }
__device__ __forceinline__ float hi_f(uint32_t u) { return __uint_as_float(u & 0xffff0000u); }
__device__ __forceinline__ float htanh(float x) {
    float y; asm("tanh.approx.f32 %0, %1;" : "=f"(y) : "f"(x)); return y;
}
__device__ __forceinline__ void mma_bf16(float& c0, float& c1, float& c2, float& c3,
                                         uint32_t a0, uint32_t a1, uint32_t a2, uint32_t a3,
                                         uint32_t b0, uint32_t b1) {
    asm volatile(
        "mma.sync.aligned.m16n8k16.row.col.f32.bf16.bf16.f32 "
        "{%0,%1,%2,%3}, {%4,%5,%6,%7}, {%8,%9}, {%0,%1,%2,%3};"
        : "+f"(c0), "+f"(c1), "+f"(c2), "+f"(c3)
        : "r"(a0), "r"(a1), "r"(a2), "r"(a3), "r"(b0), "r"(b1));
}

// ---- prep: pack w_emb and w_gcn into B-fragment order, split hi/lo bf16 ----
__global__ void prep_kernel(const float* __restrict__ w_emb,
                            const float* __restrict__ w_gcn) {
    if (blockIdx.x < 16) {
        // emb fragments: idx 0..2047 over (kt 0..3, j 0..15, lane 0..31), 2 p each
        int idx  = blockIdx.x * 128 + threadIdx.x;
        int lane = idx & 31;
        int j    = (idx >> 5) & 15;
        int kt   = idx >> 9;
        int g    = lane >> 2, tid = lane & 3;
        int n    = j * 8 + g;
        int base = ((kt * 16 + j) * 32 + lane) * 2;
        #pragma unroll
        for (int p = 0; p < 2; p++) {
            int k0 = kt * 16 + tid * 2 + p * 8;
            float v0 = w_emb[k0 * HID + n];
            float v1 = w_emb[(k0 + 1) * HID + n];
            uint32_t h0 = bf16_hi_bits(v0), h1 = bf16_hi_bits(v1);
            uint32_t l0 = bf16_hi_bits(v0 - __uint_as_float(h0 << 16));
            uint32_t l1 = bf16_hi_bits(v1 - __uint_as_float(h1 << 16));
            g_Bemb[base + p]        = (h1 << 16) | h0;
            g_Bemb[4096 + base + p] = (l1 << 16) | l0;
        }
    } else {
        // w_gcn fragments: idx2 0..16383 over (l, kt 0..7, j, lane, p)
        int idx2 = (blockIdx.x - 16) * 128 + threadIdx.x;
        int p    = idx2 & 1;
        int s    = idx2 >> 1;
        int lane = s & 31;
        int j    = (s >> 5) & 15;
        int kt   = (s >> 9) & 7;
        int l    = s >> 12;
        int g    = lane >> 2, tid = lane & 3;
        int n    = j * 8 + g;
        int k0   = kt * 16 + tid * 2 + p * 8;
        float v0 = w_gcn[l * HID * HID + k0 * HID + n];
        float v1 = w_gcn[l * HID * HID + (k0 + 1) * HID + n];
        uint32_t h0 = bf16_hi_bits(v0), h1 = bf16_hi_bits(v1);
        uint32_t l0 = bf16_hi_bits(v0 - __uint_as_float(h0 << 16));
        uint32_t l1 = bf16_hi_bits(v1 - __uint_as_float(h1 << 16));
        int base = ((kt * 16 + j) * 32 + lane) * 2 + p;
        g_Wf[l * 16384 + base]        = (h1 << 16) | h0;
        g_Wf[l * 16384 + 8192 + base] = (l1 << 16) | l0;
    }
}

__global__ __launch_bounds__(128, 3)
void gcn_critic_kernel(const float* __restrict__ cent_obs,
                       const float* __restrict__ b_emb,
                       const float* __restrict__ b_gcn,
                       const float* __restrict__ w_fc1,
                       const float* __restrict__ b_fc1,
                       float* __restrict__ out)
{
    __shared__ float s_xbar[4 * XBS];   // [graph][128] padded
    __shared__ float s_m[4 * XBS];

    const int t    = threadIdx.x;
    const int w    = t >> 5;            // warp == local graph 0..3
    const int lane = t & 31;
    const int g    = lane >> 2;
    const int tid  = lane & 3;

    const long n0 = (long)blockIdx.x * 64 + w * 16 + g;   // row of this lane
    const long n1 = n0 + 8;

    // ---- build A fragments for embedding from obs directly (split bf16) ----
    uint32_t aH[16], aL[16];
    {
        const float* r0p = cent_obs + n0 * OBS;
        const float* r1p = cent_obs + n1 * OBS;
        #pragma unroll
        for (int kt = 0; kt < 4; kt++)
            #pragma unroll
            for (int q = 0; q < 2; q++) {
                const int k = kt * 16 + tid * 2 + q * 8;
                const int idx = kt * 4 + q * 2;
                float2 v0 = *(const float2*)(r0p + k);
                float2 v1 = *(const float2*)(r1p + k);
                uint32_t h0 = cvt_bf16x2(v0.y, v0.x);
                aH[idx] = h0;
                aL[idx] = cvt_bf16x2(v0.y - hi_f(h0), v0.x - lo_f(h0));
                uint32_t h1 = cvt_bf16x2(v1.y, v1.x);
                aH[idx + 1] = h1;
                aL[idx + 1] = cvt_bf16x2(v1.y - hi_f(h1), v1.x - lo_f(h1));
            }
    }

    // ---- embedding GEMM: x (2 rows x 32 cols per lane, registers only) ----
    float xr0[32], xr1[32];
    #pragma unroll
    for (int j = 0; j < 16; j++) {
        float c0 = 0.f, c1 = 0.f, c2 = 0.f, c3 = 0.f;
        #pragma unroll
        for (int kt = 0; kt < 4; kt++) {
            const int bi = ((kt * 16 + j) * 32 + lane) * 2;
            uint2 bh = *(const uint2*)(g_Bemb + bi);
            uint2 bl = *(const uint2*)(g_Bemb + 4096 + bi);
            uint32_t a0 = aH[kt*4+0], a1 = aH[kt*4+1], a2 = aH[kt*4+2], a3 = aH[kt*4+3];
            uint32_t e0 = aL[kt*4+0], e1 = aL[kt*4+1], e2 = aL[kt*4+2], e3 = aL[kt*4+3];
            mma_bf16(c0, c1, c2, c3, a0, a1, a2, a3, bh.x, bh.y);
            mma_bf16(c0, c1, c2, c3, e0, e1, e2, e3, bh.x, bh.y);
            mma_bf16(c0, c1, c2, c3, a0, a1, a2, a3, bl.x, bl.y);
        }
        float2 be = *(const float2*)(b_emb + 8 * j + 2 * tid);
        xr0[2*j]   = c0 + be.x; xr0[2*j+1] = c1 + be.y;
        xr1[2*j]   = c2 + be.x; xr1[2*j+1] = c3 + be.y;
    }

    // ---- GCN layers (agg == per-graph mean: deg 16, norm 1/16) ----
    #pragma unroll
    for (int l = 0; l < 2; l++) {
        // xbar: reduce over the warp's 16 nodes (register + shfl over g-axis)
        {
            float s[32];
            #pragma unroll
            for (int c = 0; c < 32; c++) s[c] = xr0[c] + xr1[c];
            #pragma unroll
            for (int off = 4; off <= 16; off <<= 1)
                #pragma unroll
                for (int c = 0; c < 32; c++)
                    s[c] += __shfl_xor_sync(0xffffffffu, s[c], off);
            if (g == 0) {
                #pragma unroll
                for (int j = 0; j < 16; j++)
                    *(float2*)(s_xbar + w * XBS + 8 * j + 2 * tid) =
                        make_float2(s[2*j] * 0.0625f, s[2*j+1] * 0.0625f);
            }
        }
        __syncthreads();

        // matvec via HMMA: A = xbar (rows 0..3 real, rest zero), warp w -> jtiles 4w..4w+3
        {
            float c[4][4];
            #pragma unroll
            for (int jj = 0; jj < 4; jj++)
                c[jj][0] = c[jj][1] = c[jj][2] = c[jj][3] = 0.f;

            const uint32_t* WH = g_Wf + l * 16384;
            const uint32_t* WL = WH + 8192;
            #pragma unroll
            for (int kt = 0; kt < 8; kt++) {
                float2 v0 = make_float2(0.f, 0.f), v1 = v0;
                if (g < 4) {
                    v0 = *(const float2*)(s_xbar + g * XBS + kt * 16 + 2 * tid);
                    v1 = *(const float2*)(s_xbar + g * XBS + kt * 16 + 2 * tid + 8);
                }
                uint32_t ah0 = cvt_bf16x2(v0.y, v0.x);
                uint32_t al0 = cvt_bf16x2(v0.y - hi_f(ah0), v0.x - lo_f(ah0));
                uint32_t ah2 = cvt_bf16x2(v1.y, v1.x);
                uint32_t al2 = cvt_bf16x2(v1.y - hi_f(ah2), v1.x - lo_f(ah2));
                #pragma unroll
                for (int jj = 0; jj < 4; jj++) {
                    const int j = w * 4 + jj;
                    const int bi = ((kt * 16 + j) * 32 + lane) * 2;
                    uint2 bh = *(const uint2*)(WH + bi);
                    uint2 bl = *(const uint2*)(WL + bi);
                    mma_bf16(c[jj][0], c[jj][1], c[jj][2], c[jj][3],
                             ah0, 0u, ah2, 0u, bh.x, bh.y);
                    mma_bf16(c[jj][0], c[jj][1], c[jj][2], c[jj][3],
                             al0, 0u, al2, 0u, bh.x, bh.y);
                    mma_bf16(c[jj][0], c[jj][1], c[jj][2], c[jj][3],
                             ah0, 0u, ah2, 0u, bl.x, bl.y);
                }
            }
            if (g < 4) {
                #pragma unroll
                for (int jj = 0; jj < 4; jj++)
                    *(float2*)(s_m + g * XBS + 8 * (w * 4 + jj) + 2 * tid) =
                        make_float2(c[jj][0], c[jj][1]);
            }
        }
        __syncthreads();

        // x = tanh(x + m[graph] + b_gcn)
        #pragma unroll
        for (int j = 0; j < 16; j++) {
            float2 mg = *(const float2*)(s_m + w * XBS + 8 * j + 2 * tid);
            float2 bg = *(const float2*)(b_gcn + l * HID + 8 * j + 2 * tid);
            const float a0 = mg.x + bg.x, a1 = mg.y + bg.y;
            xr0[2*j]   = htanh(xr0[2*j]   + a0);
            xr0[2*j+1] = htanh(xr0[2*j+1] + a1);
            xr1[2*j]   = htanh(xr1[2*j]   + a0);
            xr1[2*j+1] = htanh(xr1[2*j+1] + a1);
        }
    }

    // ---- head: out[graph] = mean_{16 nodes}(x . w_fc1) + b ----
    {
        float p = 0.f;
        #pragma unroll
        for (int j = 0; j < 16; j++) {
            float2 wf = *(const float2*)(w_fc1 + 8 * j + 2 * tid);
            p += (xr0[2*j]   + xr1[2*j])   * wf.x;
            p += (xr0[2*j+1] + xr1[2*j+1]) * wf.y;
        }
        #pragma unroll
        for (int off = 16; off; off >>= 1)
            p += __shfl_xor_sync(0xffffffffu, p, off);
        if (lane == 0)
            out[blockIdx.x * 4 + w] = p * 0.0625f + b_fc1[0];
    }
}

extern "C" void kernel_launch(void* const* d_in, const int* in_sizes, int n_in,
                              void* d_out, int out_size) {
    const float* cent_obs = (const float*)d_in[0];
    const float* w_emb    = (const float*)d_in[1];
    const float* b_emb    = (const float*)d_in[2];
    const float* w_gcn    = (const float*)d_in[3];
    const float* b_gcn    = (const float*)d_in[4];
    const float* w_fc1    = (const float*)d_in[5];
    const float* b_fc1    = (const float*)d_in[6];
    // edge_src/edge_dst: fixed complete graph -> per-graph mean; unused.
    float* out = (float*)d_out;

    prep_kernel<<<144, 128>>>(w_emb, w_gcn);

    const int blocks = out_size / 4;   // 2048
    gcn_critic_kernel<<<blocks, 128>>>(
        cent_obs, b_emb, b_gcn, w_fc1, b_fc1, out);
}